// round 2
// baseline (speedup 1.0000x reference)
#include <cuda_runtime.h>
#include <math.h>

// ---------------------------------------------------------------------------
// MixtureOfMamba block, fp32. M = B*T = 4096 tokens.
// Pipeline:
//  rms1 -> in_proj GEMM -> causal dwconv+silu -> packed dt/B/C GEMM(+sigmoid dt)
//  -> sequential SSM scan -> layernorm(S=64) -> s2i GEMM -> (+D*xm)*sigmoid(gate)
//  -> out GEMM (+x residual) -> rms2 -> router(top2 softmax)
//  -> 4x [expert GEMM1(gelu), expert GEMM2(rowscale, accumulate into out)]
// ---------------------------------------------------------------------------

#define BBATCH 2
#define TSEQ   2048
#define DMODEL 1024
#define SSTATE 64
#define DINNER 2048
#define DHID   4096
#define NEXP   4
#define MTOK   (BBATCH * TSEQ)   // 4096

// ---- scratch (static device globals; no allocation allowed) ----
__device__ float g_h1[MTOK * DMODEL];                     // 16 MB
__device__ float g_xz[(size_t)MTOK * 2 * DINNER];         // 64 MB
__device__ float g_xm[(size_t)MTOK * DINNER];             // 32 MB
__device__ float g_w3[DINNER * 192];                      // packed dt|B|C weights
__device__ float g_b3[192];
__device__ float g_dtbc[MTOK * 192];                      // 3 MB
__device__ float g_y[MTOK * SSTATE];                      // 1 MB
__device__ float g_u[(size_t)MTOK * DINNER];              // 32 MB
__device__ float g_h2[MTOK * DMODEL];                     // 16 MB
__device__ float g_wf[MTOK * NEXP];
__device__ float g_hid[(size_t)MTOK * DHID];              // 64 MB

// ---------------------------------------------------------------------------
// Unified SGEMM: C[M,N] = epilogue(A[M,K] @ W[K,N])
// M is always 4096 (grid.y = 32, BM = 128). N,K arbitrary (K % 8 == 0).
// act: 0 none, 1 sigmoid, 2 gelu(exact erf), 4 sigmoid on cols < 64
// epilogue: v = act(acc + bias[n]); v *= rowscale[m*rsStride];
//           v += resid[m*N+n]; C = accumulate ? C+v : v
// ---------------------------------------------------------------------------
__device__ __forceinline__ float act_apply(float v, int act, int col) {
    if (act == 1) v = 1.f / (1.f + expf(-v));
    else if (act == 2) v = 0.5f * v * (1.f + erff(v * 0.70710678118654752f));
    else if (act == 4 && col < 64) v = 1.f / (1.f + expf(-v));
    return v;
}

__global__ __launch_bounds__(256) void sgemm_kernel(
    const float* __restrict__ A, const float* __restrict__ W,
    const float* __restrict__ bias, float* __restrict__ C,
    int N, int K, int act,
    const float* __restrict__ rowscale, int rsStride,
    const float* __restrict__ resid, int accumulate)
{
    __shared__ __align__(16) float As[2][8][128];
    __shared__ __align__(16) float Ws[2][8][128];

    const int tid  = threadIdx.x;
    const int row0 = blockIdx.y * 128;
    const int col0 = blockIdx.x * 128;

    const int ar = tid >> 1, ac = (tid & 1) << 2;   // A: 128 rows x 8 cols
    const int wr = tid >> 5, wc = (tid & 31) << 2;  // W: 8 rows x 128 cols

    const float* Ap = A + (size_t)(row0 + ar) * K + ac;
    const float* Wp = W + (size_t)wr * N + col0 + wc;
    const bool wok = (col0 + wc) < N;

    float4 a4 = *(const float4*)Ap;
    float4 w4 = wok ? *(const float4*)Wp : make_float4(0.f, 0.f, 0.f, 0.f);
    As[0][ac + 0][ar] = a4.x; As[0][ac + 1][ar] = a4.y;
    As[0][ac + 2][ar] = a4.z; As[0][ac + 3][ar] = a4.w;
    *(float4*)&Ws[0][wr][wc] = w4;
    __syncthreads();

    const int tx = (tid & 15) << 3;   // 0..120
    const int ty = (tid >> 4) << 3;   // 0..120

    float acc[8][8] = {};
    int buf = 0;
    for (int kk = 8;; kk += 8) {
        float4 a4n, w4n;
        const bool more = kk < K;
        if (more) {
            a4n = *(const float4*)(Ap + kk);
            w4n = wok ? *(const float4*)(Wp + (size_t)kk * N)
                      : make_float4(0.f, 0.f, 0.f, 0.f);
        }
#pragma unroll
        for (int k = 0; k < 8; ++k) {
            float ra[8], rw[8];
            *(float4*)&ra[0] = *(const float4*)&As[buf][k][ty];
            *(float4*)&ra[4] = *(const float4*)&As[buf][k][ty + 4];
            *(float4*)&rw[0] = *(const float4*)&Ws[buf][k][tx];
            *(float4*)&rw[4] = *(const float4*)&Ws[buf][k][tx + 4];
#pragma unroll
            for (int i = 0; i < 8; ++i)
#pragma unroll
                for (int j = 0; j < 8; ++j)
                    acc[i][j] = fmaf(ra[i], rw[j], acc[i][j]);
        }
        if (!more) break;
        buf ^= 1;
        As[buf][ac + 0][ar] = a4n.x; As[buf][ac + 1][ar] = a4n.y;
        As[buf][ac + 2][ar] = a4n.z; As[buf][ac + 3][ar] = a4n.w;
        *(float4*)&Ws[buf][wr][wc] = w4n;
        __syncthreads();
    }

#pragma unroll
    for (int i = 0; i < 8; ++i) {
        const int row = row0 + ty + i;
        const float rs = rowscale ? rowscale[(size_t)row * rsStride] : 1.f;
#pragma unroll
        for (int j = 0; j < 8; ++j) {
            const int col = col0 + tx + j;
            if (col < N) {
                float v = acc[i][j] + (bias ? bias[col] : 0.f);
                v = act_apply(v, act, col);
                v *= rs;
                const size_t o = (size_t)row * N + col;
                if (resid) v += resid[o];
                if (accumulate) C[o] += v; else C[o] = v;
            }
        }
    }
}

// ---- RMSNorm over D=1024, one block (256 thr) per token ----
__global__ void rms_kernel(const float* __restrict__ x, const float* __restrict__ w,
                           float* __restrict__ out) {
    const int m = blockIdx.x, tid = threadIdx.x;
    const float4 v = *(const float4*)&x[(size_t)m * DMODEL + tid * 4];
    float ss = v.x * v.x + v.y * v.y + v.z * v.z + v.w * v.w;
    __shared__ float red[8];
    const int lane = tid & 31, wid = tid >> 5;
#pragma unroll
    for (int o = 16; o; o >>= 1) ss += __shfl_xor_sync(0xffffffffu, ss, o);
    if (lane == 0) red[wid] = ss;
    __syncthreads();
    const float tot = red[0] + red[1] + red[2] + red[3] + red[4] + red[5] + red[6] + red[7];
    const float nr = rsqrtf(tot * (1.f / (float)DMODEL) + 1e-6f);
    const float4 wv = *(const float4*)&w[tid * 4];
    float4 o4 = make_float4(v.x * nr * wv.x, v.y * nr * wv.y,
                            v.z * nr * wv.z, v.w * nr * wv.w);
    *(float4*)&out[(size_t)m * DMODEL + tid * 4] = o4;
}

// ---- causal depthwise conv (K=3) + SiLU ----
__global__ void conv_silu_kernel(const float* __restrict__ xz,
                                 const float* __restrict__ cw,
                                 const float* __restrict__ cb,
                                 float* __restrict__ xm) {
    const int idx = blockIdx.x * 256 + threadIdx.x;   // MTOK * DINNER
    const int c = idx & (DINNER - 1);
    const int bt = idx >> 11;
    const int t = bt & (TSEQ - 1);
    const size_t rb = (size_t)bt * (2 * DINNER) + c;
    float v = cw[c * 3 + 2] * xz[rb];
    if (t >= 1) v = fmaf(cw[c * 3 + 1], xz[rb - 2 * DINNER], v);
    if (t >= 2) v = fmaf(cw[c * 3 + 0], xz[rb - 4 * DINNER], v);
    v += cb[c];
    xm[idx] = v / (1.f + expf(-v));   // silu
}

// ---- pack dt_w|bp_w|cp_w -> [2048,192] and biases -> [192] ----
__global__ void pack_w_kernel(const float* __restrict__ dw, const float* __restrict__ bw,
                              const float* __restrict__ cw, float* __restrict__ w3) {
    const int i = blockIdx.x * 256 + threadIdx.x;     // DINNER*192
    const int n = i % 192, k = i / 192;
    w3[i] = (n < 64) ? dw[k * 64 + n] : (n < 128) ? bw[k * 64 + n - 64]
                                                  : cw[k * 64 + n - 128];
}
__global__ void pack_b_kernel(const float* __restrict__ db, const float* __restrict__ bb,
                              const float* __restrict__ cb, float* __restrict__ b3) {
    const int n = threadIdx.x;
    b3[n] = (n < 64) ? db[n] : (n < 128) ? bb[n - 64] : cb[n - 128];
}

// ---- sequential SSM scan: state = state + dt*(B - state); y = C*state ----
__global__ void scan_kernel(const float* __restrict__ dtbc, float* __restrict__ y) {
    const int b = blockIdx.x, s = threadIdx.x;        // grid=B, block=64
    const size_t base  = (size_t)b * TSEQ * 192 + s;
    const size_t ybase = (size_t)b * TSEQ * SSTATE + s;
    float st = 0.f;
    for (int t0 = 0; t0 < TSEQ; t0 += 8) {
        float d[8], bb[8], cc[8];
#pragma unroll
        for (int u = 0; u < 8; ++u) {
            const size_t i = base + (size_t)(t0 + u) * 192;
            d[u] = dtbc[i]; bb[u] = dtbc[i + 64]; cc[u] = dtbc[i + 128];
        }
#pragma unroll
        for (int u = 0; u < 8; ++u) {
            st = fmaf(d[u], bb[u] - st, st);
            y[ybase + (size_t)(t0 + u) * SSTATE] = cc[u] * st;
        }
    }
}

// ---- LayerNorm over S=64 (no affine), one warp per token, in place ----
__global__ void ln_kernel(float* __restrict__ y) {
    const int m = blockIdx.x, lane = threadIdx.x;
    float v0 = y[m * 64 + lane], v1 = y[m * 64 + lane + 32];
    float s = v0 + v1;
#pragma unroll
    for (int o = 16; o; o >>= 1) s += __shfl_xor_sync(0xffffffffu, s, o);
    const float mean = s * (1.f / 64.f);
    const float d0 = v0 - mean, d1 = v1 - mean;
    float vv = d0 * d0 + d1 * d1;
#pragma unroll
    for (int o = 16; o; o >>= 1) vv += __shfl_xor_sync(0xffffffffu, vv, o);
    const float nr = rsqrtf(vv * (1.f / 64.f) + 1e-5f);
    y[m * 64 + lane] = d0 * nr;
    y[m * 64 + lane + 32] = d1 * nr;
}

// ---- u = (u + D_param*xm) * sigmoid(gate) ----
__global__ void gate_mul_kernel(const float* __restrict__ xz, const float* __restrict__ xm,
                                const float* __restrict__ Dp, float* __restrict__ u) {
    const int idx = blockIdx.x * 256 + threadIdx.x;
    const int c = idx & (DINNER - 1);
    const int bt = idx >> 11;
    const float g = xz[(size_t)bt * (2 * DINNER) + DINNER + c];
    const float v = u[idx] + Dp[c] * xm[idx];
    u[idx] = v * (1.f / (1.f + expf(-g)));
}

// ---- router: logits -> top-2 -> softmax -> dense per-expert weights ----
__global__ void route_kernel(const float* __restrict__ h2, const float* __restrict__ gw,
                             const float* __restrict__ gb, float* __restrict__ wf) {
    const int m = blockIdx.x, lane = threadIdx.x;     // 32 threads
    float a[4] = {0.f, 0.f, 0.f, 0.f};
    const float* hr = h2 + (size_t)m * DMODEL;
    for (int d = lane; d < DMODEL; d += 32) {
        const float h = hr[d];
        const float4 g = *(const float4*)&gw[d * 4];
        a[0] = fmaf(h, g.x, a[0]); a[1] = fmaf(h, g.y, a[1]);
        a[2] = fmaf(h, g.z, a[2]); a[3] = fmaf(h, g.w, a[3]);
    }
#pragma unroll
    for (int e = 0; e < 4; ++e)
#pragma unroll
        for (int o = 16; o; o >>= 1) a[e] += __shfl_xor_sync(0xffffffffu, a[e], o);
    if (lane == 0) {
        float v[4];
#pragma unroll
        for (int e = 0; e < 4; ++e) v[e] = a[e] + gb[e];
        int i0 = 0;
        for (int e = 1; e < 4; ++e) if (v[e] > v[i0]) i0 = e;      // first-on-tie
        int i1 = -1;
        for (int e = 0; e < 4; ++e)
            if (e != i0 && (i1 < 0 || v[e] > v[i1])) i1 = e;
        const float p0 = 1.f / (1.f + expf(v[i1] - v[i0]));
        float out[4] = {0.f, 0.f, 0.f, 0.f};
        out[i0] = p0; out[i1] = 1.f - p0;
#pragma unroll
        for (int e = 0; e < 4; ++e) wf[m * 4 + e] = out[e];
    }
}

// ---------------------------------------------------------------------------
extern "C" void kernel_launch(void* const* d_in, const int* in_sizes, int n_in,
                              void* d_out, int out_size) {
    (void)in_sizes; (void)n_in; (void)out_size;
    const float* x         = (const float*)d_in[0];
    const float* norm1_w   = (const float*)d_in[1];
    const float* norm2_w   = (const float*)d_in[2];
    const float* in_proj_w = (const float*)d_in[3];
    const float* in_proj_b = (const float*)d_in[4];
    const float* conv_w    = (const float*)d_in[5];
    const float* conv_b    = (const float*)d_in[6];
    const float* dt_w      = (const float*)d_in[7];
    const float* dt_b      = (const float*)d_in[8];
    const float* bp_w      = (const float*)d_in[9];
    const float* bp_b      = (const float*)d_in[10];
    const float* cp_w      = (const float*)d_in[11];
    const float* cp_b      = (const float*)d_in[12];
    const float* s2i_w     = (const float*)d_in[13];
    const float* s2i_b     = (const float*)d_in[14];
    const float* D_param   = (const float*)d_in[15];
    const float* out_w     = (const float*)d_in[16];
    const float* out_b     = (const float*)d_in[17];
    const float* gate_w    = (const float*)d_in[18];
    const float* gate_b    = (const float*)d_in[19];
    const float* e_w1      = (const float*)d_in[20];
    const float* e_b1      = (const float*)d_in[21];
    const float* e_w2      = (const float*)d_in[22];
    const float* e_b2      = (const float*)d_in[23];
    float* out = (float*)d_out;

    float *h1, *xz, *xm, *w3, *b3, *dtbc, *y, *u, *h2, *wf, *hid;
    cudaGetSymbolAddress((void**)&h1,   g_h1);
    cudaGetSymbolAddress((void**)&xz,   g_xz);
    cudaGetSymbolAddress((void**)&xm,   g_xm);
    cudaGetSymbolAddress((void**)&w3,   g_w3);
    cudaGetSymbolAddress((void**)&b3,   g_b3);
    cudaGetSymbolAddress((void**)&dtbc, g_dtbc);
    cudaGetSymbolAddress((void**)&y,    g_y);
    cudaGetSymbolAddress((void**)&u,    g_u);
    cudaGetSymbolAddress((void**)&h2,   g_h2);
    cudaGetSymbolAddress((void**)&wf,   g_wf);
    cudaGetSymbolAddress((void**)&hid,  g_hid);

    const int GY = MTOK / 128;   // 32

    // 1) h1 = rmsnorm(x)
    rms_kernel<<<MTOK, 256>>>(x, norm1_w, h1);
    // 2) xz = h1 @ in_proj_w + b    [4096, 4096]
    sgemm_kernel<<<dim3(32, GY), 256>>>(h1, in_proj_w, in_proj_b, xz,
                                        2 * DINNER, DMODEL, 0, nullptr, 0, nullptr, 0);
    // 3) xm = silu(causal dwconv(x_main) + cb)
    conv_silu_kernel<<<(MTOK * DINNER) / 256, 256>>>(xz, conv_w, conv_b, xm);
    // 4) packed dt|B|C projection, sigmoid on dt cols
    pack_w_kernel<<<(DINNER * 192) / 256, 256>>>(dt_w, bp_w, cp_w, w3);
    pack_b_kernel<<<1, 192>>>(dt_b, bp_b, cp_b, b3);
    sgemm_kernel<<<dim3(2, GY), 256>>>(xm, w3, b3, dtbc,
                                       192, DINNER, 4, nullptr, 0, nullptr, 0);
    // 5) sequential scan + layernorm
    scan_kernel<<<BBATCH, SSTATE>>>(dtbc, y);
    ln_kernel<<<MTOK, 32>>>(y);
    // 6) u = y @ s2i_w + b
    sgemm_kernel<<<dim3(16, GY), 256>>>(y, s2i_w, s2i_b, u,
                                        DINNER, SSTATE, 0, nullptr, 0, nullptr, 0);
    // 7) u = (u + D*xm) * sigmoid(gate)
    gate_mul_kernel<<<(MTOK * DINNER) / 256, 256>>>(xz, xm, D_param, u);
    // 8) out = x + u @ out_w + b     (post-mixer residual, written to d_out)
    sgemm_kernel<<<dim3(8, GY), 256>>>(u, out_w, out_b, out,
                                       DMODEL, DINNER, 0, nullptr, 0, x, 0);
    // 9) h2 = rmsnorm(out)
    rms_kernel<<<MTOK, 256>>>(out, norm2_w, h2);
    // 10) router weights
    route_kernel<<<MTOK, 32>>>(h2, gate_w, gate_b, wf);
    // 11) dense MoE: out += wf[:,e] * (gelu(h2@W1[e]+b1[e]) @ W2[e] + b2[e])
    for (int e = 0; e < NEXP; ++e) {
        sgemm_kernel<<<dim3(32, GY), 256>>>(h2, e_w1 + (size_t)e * DMODEL * DHID,
                                            e_b1 + (size_t)e * DHID, hid,
                                            DHID, DMODEL, 2, nullptr, 0, nullptr, 0);
        sgemm_kernel<<<dim3(8, GY), 256>>>(hid, e_w2 + (size_t)e * DHID * DMODEL,
                                           e_b2 + (size_t)e * DMODEL, out,
                                           DMODEL, DHID, 0, wf + e, 4, nullptr, 1);
    }
}

// round 8
// speedup vs baseline: 1.9607x; 1.9607x over previous
#include <cuda_runtime.h>
#include <cuda_bf16.h>
#include <math.h>
#include <stdint.h>

// ---------------------------------------------------------------------------
// MixtureOfMamba block. Big GEMMs: warp-level mma.sync bf16x3 (hi/lo split,
// fp32 accum) — compute_103-safe (no tcgen05). Small GEMMs fp32 FFMA.
// M = B*T = 4096.
// ---------------------------------------------------------------------------

#define BBATCH 2
#define TSEQ   2048
#define DMODEL 1024
#define SSTATE 64
#define DINNER 2048
#define DHID   4096
#define NEXP   4
#define MTOK   (BBATCH * TSEQ)   // 4096

// ---- fp32 scratch ----
__device__ float g_h1[MTOK * DMODEL];
__device__ float g_xz[(size_t)MTOK * 2 * DINNER];
__device__ float g_xm[(size_t)MTOK * DINNER];
__device__ float g_w3[DINNER * 192];
__device__ float g_b3[192];
__device__ float g_dtbc[MTOK * 192];
__device__ float g_y[MTOK * SSTATE];
__device__ float g_u[(size_t)MTOK * DINNER];
__device__ float g_h2[MTOK * DMODEL];
__device__ float g_wf[MTOK * NEXP];

// ---- bf16 hi/lo scratch ----
__device__ __nv_bfloat16 g_h1h[MTOK * DMODEL],  g_h1l[MTOK * DMODEL];
__device__ __nv_bfloat16 g_uh[(size_t)MTOK * DINNER], g_ul[(size_t)MTOK * DINNER];
__device__ __nv_bfloat16 g_h2h[MTOK * DMODEL],  g_h2l[MTOK * DMODEL];
__device__ __nv_bfloat16 g_hidh[(size_t)MTOK * DHID], g_hidl[(size_t)MTOK * DHID];
__device__ __nv_bfloat16 g_wth[DMODEL * DHID],  g_wtl[DMODEL * DHID];

// ============================================================================
// mma.sync bf16x3 GEMM.  C[M,N] = epi(A[M,K] @ W[K,N]); B given as WT[N,K].
// CTA tile 128x128, BK=32, 8 warps (2x4), 3-stage cp.async pipeline.
// ============================================================================
#define ROWB   80                       // padded smem row stride (32 bf16 + 16B)
#define MATB   (128 * ROWB)             // 10240 B per matrix tile
#define STAGE  (4 * MATB)               // Ah, Al, Bh, Bl
#define NSTAGE 3
#define GSMEM  (NSTAGE * STAGE)         // 122880 B

__device__ __forceinline__ uint32_t smem_u32(const void* p) {
    uint32_t a;
    asm("{ .reg .u64 t; cvta.to.shared.u64 t, %1; cvt.u32.u64 %0, t; }"
        : "=r"(a) : "l"(p));
    return a;
}
__device__ __forceinline__ void cp16(uint32_t dst, const void* src) {
    asm volatile("cp.async.cg.shared.global [%0], [%1], 16;"
                 :: "r"(dst), "l"((unsigned long long)__cvta_generic_to_global(src)));
}
__device__ __forceinline__ void ldm4(uint32_t addr, uint32_t* r) {
    asm volatile("ldmatrix.sync.aligned.m8n8.x4.shared.b16 {%0,%1,%2,%3}, [%4];"
                 : "=r"(r[0]), "=r"(r[1]), "=r"(r[2]), "=r"(r[3]) : "r"(addr));
}
__device__ __forceinline__ void mma_bf16(float* c, const uint32_t* a,
                                         uint32_t b0, uint32_t b1) {
    asm volatile("mma.sync.aligned.m16n8k16.row.col.f32.bf16.bf16.f32 "
                 "{%0,%1,%2,%3}, {%4,%5,%6,%7}, {%8,%9}, {%0,%1,%2,%3};"
                 : "+f"(c[0]), "+f"(c[1]), "+f"(c[2]), "+f"(c[3])
                 : "r"(a[0]), "r"(a[1]), "r"(a[2]), "r"(a[3]), "r"(b0), "r"(b1));
}

__device__ __forceinline__ void prefetch_stage(
    const __nv_bfloat16* __restrict__ Ah, const __nv_bfloat16* __restrict__ Al,
    const __nv_bfloat16* __restrict__ Bh, const __nv_bfloat16* __restrict__ Bl,
    int row0, int col0, int K, int k0, uint32_t sstage, int tid)
{
#pragma unroll
    for (int rep = 0; rep < 2; ++rep) {
        const int ch = tid + rep * 256;        // 0..511
        const int r = ch >> 2, q = ch & 3;
        const size_t goA = (size_t)(row0 + r) * K + k0 + q * 8;
        const size_t goB = (size_t)(col0 + r) * K + k0 + q * 8;
        const uint32_t so = r * ROWB + q * 16;
        cp16(sstage + so,            Ah + goA);
        cp16(sstage + MATB + so,     Al + goA);
        cp16(sstage + 2 * MATB + so, Bh + goB);
        cp16(sstage + 3 * MATB + so, Bl + goB);
    }
    asm volatile("cp.async.commit_group;" ::: "memory");
}

__global__ void __launch_bounds__(256) tc_gemm(
    const __nv_bfloat16* __restrict__ Ah, const __nv_bfloat16* __restrict__ Al,
    const __nv_bfloat16* __restrict__ Bh, const __nv_bfloat16* __restrict__ Bl,
    const float* __restrict__ bias, int N, int K, int act,
    const float* __restrict__ rowscale, int rsStride,
    const float* __restrict__ resid, float* __restrict__ C, int accumulate,
    __nv_bfloat16* __restrict__ Chi, __nv_bfloat16* __restrict__ Clo)
{
    extern __shared__ __align__(128) char smem[];
    const int tid = threadIdx.x;
    const int wid = tid >> 5, lane = tid & 31;
    const int warp_m = wid >> 2;           // 0..1
    const int warp_n = wid & 3;            // 0..3
    const int row0 = blockIdx.y * 128;
    const int col0 = blockIdx.x * 128;
    const uint32_t sb = smem_u32(smem);

    float acc[4][4][4];
#pragma unroll
    for (int i = 0; i < 4; ++i)
#pragma unroll
        for (int j = 0; j < 4; ++j)
#pragma unroll
            for (int k = 0; k < 4; ++k) acc[i][j][k] = 0.f;

    const int nChunks = K / 32;
    prefetch_stage(Ah, Al, Bh, Bl, row0, col0, K, 0, sb, tid);
    prefetch_stage(Ah, Al, Bh, Bl, row0, col0, K, 32, sb + STAGE, tid);

    const int lr = lane & 15, lch = lane >> 4;

    for (int c = 0; c < nChunks; ++c) {
        if (c + 1 == nChunks)
            asm volatile("cp.async.wait_group 0;" ::: "memory");
        else
            asm volatile("cp.async.wait_group 1;" ::: "memory");
        __syncthreads();
        if (c + 2 < nChunks)
            prefetch_stage(Ah, Al, Bh, Bl, row0, col0, K, (c + 2) * 32,
                           sb + ((c + 2) % NSTAGE) * STAGE, tid);

        const uint32_t stg = sb + (c % NSTAGE) * STAGE;
        const uint32_t aBase  = stg;
        const uint32_t alBase = stg + MATB;
        const uint32_t bBase  = stg + 2 * MATB;
        const uint32_t blBase = stg + 3 * MATB;

#pragma unroll
        for (int h = 0; h < 2; ++h) {
            uint32_t aH[4][4], aL[4][4], bHf[2][4], bLf[2][4];
#pragma unroll
            for (int mt = 0; mt < 4; ++mt) {
                const uint32_t off =
                    (uint32_t)((warp_m * 64 + mt * 16 + lr) * ROWB + h * 32 + lch * 16);
                ldm4(aBase + off, aH[mt]);
                ldm4(alBase + off, aL[mt]);
            }
#pragma unroll
            for (int j2 = 0; j2 < 2; ++j2) {
                const uint32_t off =
                    (uint32_t)((warp_n * 32 + j2 * 16 + lr) * ROWB + h * 32 + lch * 16);
                ldm4(bBase + off, bHf[j2]);
                ldm4(blBase + off, bLf[j2]);
            }
#pragma unroll
            for (int mt = 0; mt < 4; ++mt)
#pragma unroll
                for (int nt = 0; nt < 4; ++nt) {
                    const int j2 = nt >> 1, sub = nt & 1;
                    const uint32_t bh0 = bHf[j2][sub], bh1 = bHf[j2][sub + 2];
                    const uint32_t bl0 = bLf[j2][sub], bl1 = bLf[j2][sub + 2];
                    mma_bf16(acc[mt][nt], aH[mt], bh0, bh1);
                    mma_bf16(acc[mt][nt], aH[mt], bl0, bl1);
                    mma_bf16(acc[mt][nt], aL[mt], bh0, bh1);
                }
        }
        __syncthreads();
    }

    // ---- epilogue ----
    const int lr4 = lane >> 2, lc2 = (lane & 3) * 2;
#pragma unroll
    for (int mt = 0; mt < 4; ++mt) {
        const int rA = row0 + warp_m * 64 + mt * 16 + lr4;
        const int rB = rA + 8;
        const float rsA = rowscale ? rowscale[(size_t)rA * rsStride] : 1.f;
        const float rsB = rowscale ? rowscale[(size_t)rB * rsStride] : 1.f;
#pragma unroll
        for (int nt = 0; nt < 4; ++nt) {
            const int col = col0 + warp_n * 32 + nt * 8 + lc2;
            float b0 = bias ? bias[col] : 0.f;
            float b1 = bias ? bias[col + 1] : 0.f;
#pragma unroll
            for (int half = 0; half < 2; ++half) {
                const int row = half ? rB : rA;
                const float rs = half ? rsB : rsA;
                float v0 = acc[mt][nt][half * 2 + 0] + b0;
                float v1 = acc[mt][nt][half * 2 + 1] + b1;
                if (act == 2) {
                    v0 = 0.5f * v0 * (1.f + erff(v0 * 0.70710678118654752f));
                    v1 = 0.5f * v1 * (1.f + erff(v1 * 0.70710678118654752f));
                }
                v0 *= rs; v1 *= rs;
                const size_t o = (size_t)row * N + col;
                if (resid) {
                    const float2 r2 = *(const float2*)(resid + o);
                    v0 += r2.x; v1 += r2.y;
                }
                if (C) {
                    if (accumulate) {
                        float2 c2 = *(const float2*)(C + o);
                        c2.x += v0; c2.y += v1;
                        *(float2*)(C + o) = c2;
                    } else {
                        *(float2*)(C + o) = make_float2(v0, v1);
                    }
                }
                if (Chi) {
                    const __nv_bfloat16 h0 = __float2bfloat16(v0);
                    const __nv_bfloat16 h1 = __float2bfloat16(v1);
                    *(__nv_bfloat162*)(Chi + o) = __nv_bfloat162(h0, h1);
                    const __nv_bfloat16 l0 = __float2bfloat16(v0 - __bfloat162float(h0));
                    const __nv_bfloat16 l1 = __float2bfloat16(v1 - __bfloat162float(h1));
                    *(__nv_bfloat162*)(Clo + o) = __nv_bfloat162(l0, l1);
                }
            }
        }
    }
}

// ============================================================================
// conversion kernels
// ============================================================================
__global__ void split_kernel(const float* __restrict__ x, __nv_bfloat16* __restrict__ h,
                             __nv_bfloat16* __restrict__ l) {
    const int i = blockIdx.x * 256 + threadIdx.x;
    const float v = x[i];
    const __nv_bfloat16 hi = __float2bfloat16(v);
    h[i] = hi;
    l[i] = __float2bfloat16(v - __bfloat162float(hi));
}
// W fp32 [K,N] -> WT bf16 hi/lo [N,K]
__global__ void convT_kernel(const float* __restrict__ W, __nv_bfloat16* __restrict__ Th,
                             __nv_bfloat16* __restrict__ Tl, int K, int N) {
    __shared__ float t[32][33];
    const int n0 = blockIdx.x * 32, k0 = blockIdx.y * 32;
    const int tx = threadIdx.x, ty = threadIdx.y;
#pragma unroll
    for (int i = 0; i < 32; i += 8)
        t[ty + i][tx] = W[(size_t)(k0 + ty + i) * N + n0 + tx];
    __syncthreads();
#pragma unroll
    for (int i = 0; i < 32; i += 8) {
        const float v = t[tx][ty + i];
        const __nv_bfloat16 hi = __float2bfloat16(v);
        const size_t o = (size_t)(n0 + ty + i) * K + k0 + tx;
        Th[o] = hi;
        Tl[o] = __float2bfloat16(v - __bfloat162float(hi));
    }
}

// ============================================================================
// fp32 SGEMM (small GEMMs: dt/B/C projection, s2i)
// ============================================================================
__global__ __launch_bounds__(256) void sgemm_kernel(
    const float* __restrict__ A, const float* __restrict__ W,
    const float* __restrict__ bias, float* __restrict__ C,
    int N, int K, int act)
{
    __shared__ __align__(16) float As[2][8][128];
    __shared__ __align__(16) float Ws[2][8][128];
    const int tid  = threadIdx.x;
    const int row0 = blockIdx.y * 128;
    const int col0 = blockIdx.x * 128;
    const int ar = tid >> 1, ac = (tid & 1) << 2;
    const int wr = tid >> 5, wc = (tid & 31) << 2;
    const float* Ap = A + (size_t)(row0 + ar) * K + ac;
    const float* Wp = W + (size_t)wr * N + col0 + wc;
    const bool wok = (col0 + wc) < N;

    float4 a4 = *(const float4*)Ap;
    float4 w4 = wok ? *(const float4*)Wp : make_float4(0.f, 0.f, 0.f, 0.f);
    As[0][ac + 0][ar] = a4.x; As[0][ac + 1][ar] = a4.y;
    As[0][ac + 2][ar] = a4.z; As[0][ac + 3][ar] = a4.w;
    *(float4*)&Ws[0][wr][wc] = w4;
    __syncthreads();

    const int tx = (tid & 15) << 3;
    const int ty = (tid >> 4) << 3;
    float acc[8][8] = {};
    int buf = 0;
    for (int kk = 8;; kk += 8) {
        float4 a4n, w4n;
        const bool more = kk < K;
        if (more) {
            a4n = *(const float4*)(Ap + kk);
            w4n = wok ? *(const float4*)(Wp + (size_t)kk * N)
                      : make_float4(0.f, 0.f, 0.f, 0.f);
        }
#pragma unroll
        for (int k = 0; k < 8; ++k) {
            float ra[8], rw[8];
            *(float4*)&ra[0] = *(const float4*)&As[buf][k][ty];
            *(float4*)&ra[4] = *(const float4*)&As[buf][k][ty + 4];
            *(float4*)&rw[0] = *(const float4*)&Ws[buf][k][tx];
            *(float4*)&rw[4] = *(const float4*)&Ws[buf][k][tx + 4];
#pragma unroll
            for (int i = 0; i < 8; ++i)
#pragma unroll
                for (int j = 0; j < 8; ++j)
                    acc[i][j] = fmaf(ra[i], rw[j], acc[i][j]);
        }
        if (!more) break;
        buf ^= 1;
        As[buf][ac + 0][ar] = a4n.x; As[buf][ac + 1][ar] = a4n.y;
        As[buf][ac + 2][ar] = a4n.z; As[buf][ac + 3][ar] = a4n.w;
        *(float4*)&Ws[buf][wr][wc] = w4n;
        __syncthreads();
    }
#pragma unroll
    for (int i = 0; i < 8; ++i) {
        const int row = row0 + ty + i;
#pragma unroll
        for (int j = 0; j < 8; ++j) {
            const int col = col0 + tx + j;
            if (col < N) {
                float v = acc[i][j] + (bias ? bias[col] : 0.f);
                if (act == 4 && col < 64) v = 1.f / (1.f + expf(-v));
                C[(size_t)row * N + col] = v;
            }
        }
    }
}

// ============================================================================
// pointwise / small kernels
// ============================================================================
__global__ void rms_kernel(const float* __restrict__ x, const float* __restrict__ w,
                           float* __restrict__ out) {
    const int m = blockIdx.x, tid = threadIdx.x;
    const float4 v = *(const float4*)&x[(size_t)m * DMODEL + tid * 4];
    float ss = v.x * v.x + v.y * v.y + v.z * v.z + v.w * v.w;
    __shared__ float red[8];
    const int lane = tid & 31, wid = tid >> 5;
#pragma unroll
    for (int o = 16; o; o >>= 1) ss += __shfl_xor_sync(0xffffffffu, ss, o);
    if (lane == 0) red[wid] = ss;
    __syncthreads();
    const float tot = red[0] + red[1] + red[2] + red[3] + red[4] + red[5] + red[6] + red[7];
    const float nr = rsqrtf(tot * (1.f / (float)DMODEL) + 1e-6f);
    const float4 wv = *(const float4*)&w[tid * 4];
    *(float4*)&out[(size_t)m * DMODEL + tid * 4] =
        make_float4(v.x * nr * wv.x, v.y * nr * wv.y, v.z * nr * wv.z, v.w * nr * wv.w);
}

__global__ void conv_silu_kernel(const float* __restrict__ xz,
                                 const float* __restrict__ cw,
                                 const float* __restrict__ cb,
                                 float* __restrict__ xm) {
    const int idx = blockIdx.x * 256 + threadIdx.x;
    const int c = idx & (DINNER - 1);
    const int bt = idx >> 11;
    const int t = bt & (TSEQ - 1);
    const size_t rb = (size_t)bt * (2 * DINNER) + c;
    float v = cw[c * 3 + 2] * xz[rb];
    if (t >= 1) v = fmaf(cw[c * 3 + 1], xz[rb - 2 * DINNER], v);
    if (t >= 2) v = fmaf(cw[c * 3 + 0], xz[rb - 4 * DINNER], v);
    v += cb[c];
    xm[idx] = v / (1.f + expf(-v));
}

__global__ void pack_w_kernel(const float* __restrict__ dw, const float* __restrict__ bw,
                              const float* __restrict__ cw, float* __restrict__ w3) {
    const int i = blockIdx.x * 256 + threadIdx.x;
    const int n = i % 192, k = i / 192;
    w3[i] = (n < 64) ? dw[k * 64 + n] : (n < 128) ? bw[k * 64 + n - 64]
                                                  : cw[k * 64 + n - 128];
}
__global__ void pack_b_kernel(const float* __restrict__ db, const float* __restrict__ bb,
                              const float* __restrict__ cb, float* __restrict__ b3) {
    const int n = threadIdx.x;
    b3[n] = (n < 64) ? db[n] : (n < 128) ? bb[n - 64] : cb[n - 128];
}

__global__ void scan_kernel(const float* __restrict__ dtbc, float* __restrict__ y) {
    const int b = blockIdx.x, s = threadIdx.x;
    const size_t base  = (size_t)b * TSEQ * 192 + s;
    const size_t ybase = (size_t)b * TSEQ * SSTATE + s;
    float st = 0.f;
    for (int t0 = 0; t0 < TSEQ; t0 += 8) {
        float d[8], bb[8], cc[8];
#pragma unroll
        for (int u = 0; u < 8; ++u) {
            const size_t i = base + (size_t)(t0 + u) * 192;
            d[u] = dtbc[i]; bb[u] = dtbc[i + 64]; cc[u] = dtbc[i + 128];
        }
#pragma unroll
        for (int u = 0; u < 8; ++u) {
            st = fmaf(d[u], bb[u] - st, st);
            y[ybase + (size_t)(t0 + u) * SSTATE] = cc[u] * st;
        }
    }
}

__global__ void ln_kernel(float* __restrict__ y) {
    const int m = blockIdx.x, lane = threadIdx.x;
    float v0 = y[m * 64 + lane], v1 = y[m * 64 + lane + 32];
    float s = v0 + v1;
#pragma unroll
    for (int o = 16; o; o >>= 1) s += __shfl_xor_sync(0xffffffffu, s, o);
    const float mean = s * (1.f / 64.f);
    const float d0 = v0 - mean, d1 = v1 - mean;
    float vv = d0 * d0 + d1 * d1;
#pragma unroll
    for (int o = 16; o; o >>= 1) vv += __shfl_xor_sync(0xffffffffu, vv, o);
    const float nr = rsqrtf(vv * (1.f / 64.f) + 1e-5f);
    y[m * 64 + lane] = d0 * nr;
    y[m * 64 + lane + 32] = d1 * nr;
}

__global__ void gate_mul_kernel(const float* __restrict__ xz, const float* __restrict__ xm,
                                const float* __restrict__ Dp, float* __restrict__ u) {
    const int idx = blockIdx.x * 256 + threadIdx.x;
    const int c = idx & (DINNER - 1);
    const int bt = idx >> 11;
    const float g = xz[(size_t)bt * (2 * DINNER) + DINNER + c];
    const float v = u[idx] + Dp[c] * xm[idx];
    u[idx] = v * (1.f / (1.f + expf(-g)));
}

__global__ void route_kernel(const float* __restrict__ h2, const float* __restrict__ gw,
                             const float* __restrict__ gb, float* __restrict__ wf) {
    const int m = blockIdx.x, lane = threadIdx.x;
    float a[4] = {0.f, 0.f, 0.f, 0.f};
    const float* hr = h2 + (size_t)m * DMODEL;
    for (int d = lane; d < DMODEL; d += 32) {
        const float h = hr[d];
        const float4 g = *(const float4*)&gw[d * 4];
        a[0] = fmaf(h, g.x, a[0]); a[1] = fmaf(h, g.y, a[1]);
        a[2] = fmaf(h, g.z, a[2]); a[3] = fmaf(h, g.w, a[3]);
    }
#pragma unroll
    for (int e = 0; e < 4; ++e)
#pragma unroll
        for (int o = 16; o; o >>= 1) a[e] += __shfl_xor_sync(0xffffffffu, a[e], o);
    if (lane == 0) {
        float v[4];
#pragma unroll
        for (int e = 0; e < 4; ++e) v[e] = a[e] + gb[e];
        int i0 = 0;
        for (int e = 1; e < 4; ++e) if (v[e] > v[i0]) i0 = e;
        int i1 = -1;
        for (int e = 0; e < 4; ++e)
            if (e != i0 && (i1 < 0 || v[e] > v[i1])) i1 = e;
        const float p0 = 1.f / (1.f + expf(v[i1] - v[i0]));
        float out[4] = {0.f, 0.f, 0.f, 0.f};
        out[i0] = p0; out[i1] = 1.f - p0;
#pragma unroll
        for (int e = 0; e < 4; ++e) wf[m * 4 + e] = out[e];
    }
}

// ============================================================================
extern "C" void kernel_launch(void* const* d_in, const int* in_sizes, int n_in,
                              void* d_out, int out_size) {
    (void)in_sizes; (void)n_in; (void)out_size;
    const float* x         = (const float*)d_in[0];
    const float* norm1_w   = (const float*)d_in[1];
    const float* norm2_w   = (const float*)d_in[2];
    const float* in_proj_w = (const float*)d_in[3];
    const float* in_proj_b = (const float*)d_in[4];
    const float* conv_w    = (const float*)d_in[5];
    const float* conv_b    = (const float*)d_in[6];
    const float* dt_w      = (const float*)d_in[7];
    const float* dt_b      = (const float*)d_in[8];
    const float* bp_w      = (const float*)d_in[9];
    const float* bp_b      = (const float*)d_in[10];
    const float* cp_w      = (const float*)d_in[11];
    const float* cp_b      = (const float*)d_in[12];
    const float* s2i_w     = (const float*)d_in[13];
    const float* s2i_b     = (const float*)d_in[14];
    const float* D_param   = (const float*)d_in[15];
    const float* out_w     = (const float*)d_in[16];
    const float* out_b     = (const float*)d_in[17];
    const float* gate_w    = (const float*)d_in[18];
    const float* gate_b    = (const float*)d_in[19];
    const float* e_w1      = (const float*)d_in[20];
    const float* e_b1      = (const float*)d_in[21];
    const float* e_w2      = (const float*)d_in[22];
    const float* e_b2      = (const float*)d_in[23];
    float* out = (float*)d_out;

    float *h1, *xz, *xm, *w3, *b3, *dtbc, *y, *u, *h2, *wf;
    __nv_bfloat16 *h1h, *h1l, *uh, *ul, *h2h, *h2l, *hidh, *hidl, *wth, *wtl;
    cudaGetSymbolAddress((void**)&h1,   g_h1);
    cudaGetSymbolAddress((void**)&xz,   g_xz);
    cudaGetSymbolAddress((void**)&xm,   g_xm);
    cudaGetSymbolAddress((void**)&w3,   g_w3);
    cudaGetSymbolAddress((void**)&b3,   g_b3);
    cudaGetSymbolAddress((void**)&dtbc, g_dtbc);
    cudaGetSymbolAddress((void**)&y,    g_y);
    cudaGetSymbolAddress((void**)&u,    g_u);
    cudaGetSymbolAddress((void**)&h2,   g_h2);
    cudaGetSymbolAddress((void**)&wf,   g_wf);
    cudaGetSymbolAddress((void**)&h1h,  g_h1h);
    cudaGetSymbolAddress((void**)&h1l,  g_h1l);
    cudaGetSymbolAddress((void**)&uh,   g_uh);
    cudaGetSymbolAddress((void**)&ul,   g_ul);
    cudaGetSymbolAddress((void**)&h2h,  g_h2h);
    cudaGetSymbolAddress((void**)&h2l,  g_h2l);
    cudaGetSymbolAddress((void**)&hidh, g_hidh);
    cudaGetSymbolAddress((void**)&hidl, g_hidl);
    cudaGetSymbolAddress((void**)&wth,  g_wth);
    cudaGetSymbolAddress((void**)&wtl,  g_wtl);

    cudaFuncSetAttribute(tc_gemm, cudaFuncAttributeMaxDynamicSharedMemorySize, GSMEM);

    const int GY = MTOK / 128;            // 32
    const dim3 tb(32, 8);

    // 1) h1 = rmsnorm(x); split
    rms_kernel<<<MTOK, 256>>>(x, norm1_w, h1);
    split_kernel<<<(MTOK * DMODEL) / 256, 256>>>(h1, h1h, h1l);
    // 2) xz = h1 @ in_proj_w + b   (K=1024, N=4096)
    convT_kernel<<<dim3(4096 / 32, 1024 / 32), tb>>>(in_proj_w, wth, wtl, 1024, 4096);
    tc_gemm<<<dim3(32, GY), 256, GSMEM>>>(h1h, h1l, wth, wtl, in_proj_b,
                                          4096, 1024, 0, nullptr, 0, nullptr, xz, 0,
                                          nullptr, nullptr);
    // 3) xm = silu(dwconv(x_main))
    conv_silu_kernel<<<(MTOK * DINNER) / 256, 256>>>(xz, conv_w, conv_b, xm);
    // 4) dt|B|C projection (fp32), sigmoid on dt cols
    pack_w_kernel<<<(DINNER * 192) / 256, 256>>>(dt_w, bp_w, cp_w, w3);
    pack_b_kernel<<<1, 192>>>(dt_b, bp_b, cp_b, b3);
    sgemm_kernel<<<dim3(2, GY), 256>>>(xm, w3, b3, dtbc, 192, DINNER, 4);
    // 5) scan + layernorm
    scan_kernel<<<BBATCH, SSTATE>>>(dtbc, y);
    ln_kernel<<<MTOK, 32>>>(y);
    // 6) u = y @ s2i_w + b (fp32, K=64)
    sgemm_kernel<<<dim3(16, GY), 256>>>(y, s2i_w, s2i_b, u, DINNER, SSTATE, 0);
    // 7) u = (u + D*xm) * sigmoid(gate); split
    gate_mul_kernel<<<(MTOK * DINNER) / 256, 256>>>(xz, xm, D_param, u);
    split_kernel<<<(MTOK * DINNER) / 256, 256>>>(u, uh, ul);
    // 8) out = x + u @ out_w + b   (K=2048, N=1024)
    convT_kernel<<<dim3(1024 / 32, 2048 / 32), tb>>>(out_w, wth, wtl, 2048, 1024);
    tc_gemm<<<dim3(8, GY), 256, GSMEM>>>(uh, ul, wth, wtl, out_b,
                                         1024, 2048, 0, nullptr, 0, x, out, 0,
                                         nullptr, nullptr);
    // 9) h2 = rmsnorm(out); split
    rms_kernel<<<MTOK, 256>>>(out, norm2_w, h2);
    split_kernel<<<(MTOK * DMODEL) / 256, 256>>>(h2, h2h, h2l);
    // 10) router
    route_kernel<<<MTOK, 32>>>(h2, gate_w, gate_b, wf);
    // 11) dense MoE
    for (int e = 0; e < NEXP; ++e) {
        convT_kernel<<<dim3(4096 / 32, 1024 / 32), tb>>>(
            e_w1 + (size_t)e * DMODEL * DHID, wth, wtl, 1024, 4096);
        tc_gemm<<<dim3(32, GY), 256, GSMEM>>>(h2h, h2l, wth, wtl,
                                              e_b1 + (size_t)e * DHID,
                                              4096, 1024, 2, nullptr, 0, nullptr,
                                              nullptr, 0, hidh, hidl);
        convT_kernel<<<dim3(1024 / 32, 4096 / 32), tb>>>(
            e_w2 + (size_t)e * DHID * DMODEL, wth, wtl, 4096, 1024);
        tc_gemm<<<dim3(8, GY), 256, GSMEM>>>(hidh, hidl, wth, wtl,
                                             e_b2 + (size_t)e * DMODEL,
                                             1024, 4096, 0, wf + e, 4, nullptr,
                                             out, 1, nullptr, nullptr);
    }
}